// round 17
// baseline (speedup 1.0000x reference)
#include <cuda_runtime.h>
#include <cuda_bf16.h>
#include <cstdint>

// ---------------- problem constants ----------------
#define BB 8
#define DD 64
#define TT 8192
#define KK 1024
#define NROWS 65536
#define NZ 4194304
#define THREADS 128
#define MROWS 64              // rows per CTA (one m16 tile per warp)
#define NBLOCKS 1024
#define NC 32                 // codes per chunk
#define NCHUNKS 32
#define CAND_CAP 32           // candidate slots per row (overflow -> exact fallback)

// ---------------- device scratch (no allocs allowed) ----------------
__device__ float g_wnorm[KK];
__device__ float g_partial[NBLOCKS];
__device__ unsigned int g_ticket;     // zero-init; reset by last block every run
__device__ __align__(16) __nv_bfloat16 g_wh[KK * DD];   // fragment-permuted bf16(W)

// ---------------- static SMEM layout (36096 B -> 5 CTAs/SM, regs bind) ----------------
#define B_ROW_STRIDE 144              // 128B data + 16B pad -> conflict-free LDS.128
#define B_BUF (NC * B_ROW_STRIDE)     // 4608 B per buffer
#define Z_STRIDE 68                   // floats per z row (16B-aligned rows)
#define SM_Z    0                     // 64 x 68 x 4 = 17408 B (resident all kernel)
#define SM_B    17408                 // 2 buffers: 9216 B
#define SM_WN   26624                 // wnorm[1024] fp32: 4096 B
#define SM_ZN   30720                 // znorm[64]: 256 B
#define SM_E    30976                 // window D[64]: 256 B
#define SM_CNT  31232                 // candidate counters[64]: 256 B
#define SM_CAND 31488                 // cand idx u16 [64][32]: 4096 B
#define SM_RED  35584                 // loss reduction[128]: 512 B
#define SM_SIZE 36096

// ---------------- helpers ----------------
__device__ __forceinline__ uint32_t smem_u32(const void* p) {
    uint32_t a;
    asm("{ .reg .u64 t; cvta.to.shared.u64 t, %1; cvt.u32.u64 %0, t; }" : "=r"(a) : "l"(p));
    return a;
}
__device__ __forceinline__ void cp_async16(uint32_t dst, const void* src) {
    asm volatile("cp.async.cg.shared.global [%0], [%1], 16;" :: "r"(dst), "l"(src));
}
#define CP_COMMIT()  asm volatile("cp.async.commit_group;" ::: "memory")
#define CP_WAIT(n)   asm volatile("cp.async.wait_group %0;" :: "n"(n) : "memory")

// packed f32x2
__device__ __forceinline__ unsigned long long pk2(float lo, float hi) {
    unsigned long long r;
    asm("mov.b64 %0, {%1, %2};" : "=l"(r) : "f"(lo), "f"(hi));
    return r;
}
__device__ __forceinline__ void unpk2(unsigned long long v, float& lo, float& hi) {
    asm("mov.b64 {%0, %1}, %2;" : "=f"(lo), "=f"(hi) : "l"(v));
}
__device__ __forceinline__ unsigned long long fma2(unsigned long long a, unsigned long long b, unsigned long long c) {
    unsigned long long d;
    asm("fma.rn.f32x2 %0, %1, %2, %3;" : "=l"(d) : "l"(a), "l"(b), "l"(c));
    return d;
}
__device__ __forceinline__ unsigned long long add2(unsigned long long a, unsigned long long b) {
    unsigned long long d;
    asm("add.rn.f32x2 %0, %1, %2;" : "=l"(d) : "l"(a), "l"(b));
    return d;
}

// m16n8k16 bf16 MMA, fp32 accumulate
#define MMA_BF16(acc, a, b) \
    asm volatile("mma.sync.aligned.m16n8k16.row.col.f32.bf16.bf16.f32 " \
        "{%0,%1,%2,%3},{%4,%5,%6,%7},{%8,%9},{%0,%1,%2,%3};" \
        : "+f"((acc)[0]), "+f"((acc)[1]), "+f"((acc)[2]), "+f"((acc)[3]) \
        : "r"((a)[0]), "r"((a)[1]), "r"((a)[2]), "r"((a)[3]), \
          "r"((b)[0]), "r"((b)[1]))

__device__ __forceinline__ uint32_t hi2(float a, float b) {
    __nv_bfloat16 ha = __float2bfloat16(a), hb = __float2bfloat16(b);
    return (uint32_t)__bfloat16_as_ushort(ha) | ((uint32_t)__bfloat16_as_ushort(hb) << 16);
}

// fragment permutation: element kk (0..63) of a W row -> bf16 slot
__device__ __host__ __forceinline__ int permidx(int kk) {
    int kt = kk >> 4, r = kk & 15;
    int half = r >> 3, s = r & 7, tq = s >> 1, e = s & 1;
    return tq * 16 + kt * 4 + half * 2 + e;
}

// ---------------- prep: wnorm (R1-identical rounding order) + permuted bf16 hi of W ----------------
__global__ void vq_prep_kernel(const float* __restrict__ W) {
    int k = blockIdx.x * blockDim.x + threadIdx.x;
    if (k >= KK) return;
    const float4* wr = reinterpret_cast<const float4*>(W + (size_t)k * DD);
    float t32[32];
    uint32_t uh[32];
#pragma unroll
    for (int i = 0; i < 32; i++) uh[i] = 0;
#pragma unroll
    for (int j = 0; j < 8; j++) {
        float4 va = wr[j];
        float4 vb = wr[j + 8];
        float av[4] = {va.x, va.y, va.z, va.w};
        float bv[4] = {vb.x, vb.y, vb.z, vb.w};
#pragma unroll
        for (int q = 0; q < 4; q++) {
            t32[4 * j + q] = __fadd_rn(__fmul_rn(av[q], av[q]), __fmul_rn(bv[q], bv[q]));
            {
                int idx = permidx(4 * j + q);
                __nv_bfloat16 h = __float2bfloat16(av[q]);
                uh[idx >> 1] |= (uint32_t)__bfloat16_as_ushort(h) << (16 * (idx & 1));
            }
            {
                int idx = permidx(4 * j + q + 32);
                __nv_bfloat16 h = __float2bfloat16(bv[q]);
                uh[idx >> 1] |= (uint32_t)__bfloat16_as_ushort(h) << (16 * (idx & 1));
            }
        }
    }
#pragma unroll
    for (int off = 16; off >= 1; off >>= 1) {
#pragma unroll
        for (int j = 0; j < 16; j++) {
            if (j < off) t32[j] = __fadd_rn(t32[j], t32[j + off]);
        }
    }
    g_wnorm[k] = t32[0];
    uint4* dh = reinterpret_cast<uint4*>(g_wh + (size_t)k * DD);
#pragma unroll
    for (int i = 0; i < 8; i++)
        dh[i] = make_uint4(uh[4 * i], uh[4 * i + 1], uh[4 * i + 2], uh[4 * i + 3]);
}

// ---------------- chunk prefetch via cp.async (hi only: 256 x 16B) ----------------
__device__ __forceinline__ void issue_chunk(uint32_t sb, int chunk, int buf, int tid) {
    const uint4* srcH = reinterpret_cast<const uint4*>(g_wh + (size_t)chunk * NC * DD);
    uint32_t dH = sb + SM_B + buf * B_BUF;
#pragma unroll
    for (int i = 0; i < 2; i++) {
        int idx = tid + i * THREADS;          // 0..255: row = idx/8, 16B col = idx%8
        uint32_t off = (uint32_t)(idx >> 3) * B_ROW_STRIDE + (uint32_t)(idx & 7) * 16;
        cp_async16(dH + off, srcH + idx);
    }
}

// ---------------- 4 approx dists for one nt (bitwise identical both sweeps) ----------------
__device__ __forceinline__ void nt_dists(
    const char* smp, const char* bbase, int c, int nt, int g, int t,
    const uint32_t ah[4][4],
    unsigned long long zpkA, unsigned long long zpkB, unsigned long long NEG2,
    float& d0, float& d1, float& d2, float& d3)
{
    const char* rowp = bbase + (nt * 8 + g) * B_ROW_STRIDE + t * 32;
    uint4 h0 = *reinterpret_cast<const uint4*>(rowp);
    uint4 h1 = *reinterpret_cast<const uint4*>(rowp + 16);
    uint32_t bh[4][2] = {{h0.x, h0.y}, {h0.z, h0.w}, {h1.x, h1.y}, {h1.z, h1.w}};
    float acc[4] = {0.f, 0.f, 0.f, 0.f};
#pragma unroll
    for (int kt = 0; kt < 4; kt++) MMA_BF16(acc, ah[kt], bh[kt]);
    const int cb = c * NC + nt * 8 + 2 * t;
    unsigned long long wpk = *reinterpret_cast<const unsigned long long*>(smp + SM_WN + (size_t)cb * 4);
    unsigned long long dA = add2(fma2(pk2(acc[0], acc[1]), NEG2, zpkA), wpk);
    unsigned long long dB = add2(fma2(pk2(acc[2], acc[3]), NEG2, zpkB), wpk);
    unpk2(dA, d0, d1);
    unpk2(dB, d2, d3);
}

// ---------------- exact distance (R10-12-validated code-exact refine) ----------------
__device__ __forceinline__ float exact_dist(const float* zr, int idx, float zn,
                                            const float* sWN, const float* W) {
    const float4* wr4 = reinterpret_cast<const float4*>(W + (size_t)idx * DD);
    float acc = 0.0f;
#pragma unroll
    for (int q = 0; q < 16; q++) {
        float4 wv = __ldg(wr4 + q);
        acc = __fmaf_rn(zr[4 * q],     wv.x, acc);
        acc = __fmaf_rn(zr[4 * q + 1], wv.y, acc);
        acc = __fmaf_rn(zr[4 * q + 2], wv.z, acc);
        acc = __fmaf_rn(zr[4 * q + 3], wv.w, acc);
    }
    return __fadd_rn(__fmaf_rn(acc, -2.0f, zn), sWN[idx]);
}

// ---------------- main kernel ----------------
__global__ __launch_bounds__(THREADS, 5)
void vq_main_kernel(const float* __restrict__ z,
                    const float* __restrict__ W,
                    float* __restrict__ out_zq,
                    float* __restrict__ out_codes,
                    float* __restrict__ out_loss) {
    __shared__ __align__(16) char smp[SM_SIZE];
    const uint32_t sb = smem_u32(smp);

    const int tid = threadIdx.x;
    const int w = tid >> 5;
    const int l = tid & 31;
    const int g = l >> 2;
    const int t = l & 3;
    int* cnts = reinterpret_cast<int*>(smp + SM_CNT);
    unsigned short* clist = reinterpret_cast<unsigned short*>(smp + SM_CAND);

    // ---- stage z rows (2 threads/row), znorm (R1-identical order), window D ----
    {
        const int row = tid >> 1;                  // 0..63
        const int half = tid & 1;                  // cols half*32 .. +31
        const int grow = blockIdx.x * MROWS + row;
        const float* zp = z + (size_t)(grow >> 13) * DD * TT + (grow & (TT - 1));
        float* zr = reinterpret_cast<float*>(smp) + row * Z_STRIDE + half * 32;
        float sq[16];
        float zh2 = 0.0f, zl2 = 0.0f;
#pragma unroll
        for (int j = 0; j < 16; j++) {
            float v0 = zp[(size_t)(half * 32 + 2 * j) * TT];
            float v1 = zp[(size_t)(half * 32 + 2 * j + 1) * TT];
            zr[2 * j] = v0;
            zr[2 * j + 1] = v1;
            sq[j] = __fadd_rn(__fmul_rn(v0, v0), __fmul_rn(v1, v1));
            float h0 = __bfloat162float(__float2bfloat16(v0));
            float h1 = __bfloat162float(__float2bfloat16(v1));
            float l0 = v0 - h0, l1 = v1 - h1;
            zh2 += h0 * h0 + h1 * h1;
            zl2 += l0 * l0 + l1 * l1;
        }
#pragma unroll
        for (int j = 0; j < 16; j++) {
            float other = __shfl_xor_sync(0xffffffff, sq[j], 1);
            sq[j] = half ? __fadd_rn(other, sq[j]) : __fadd_rn(sq[j], other);
        }
#pragma unroll
        for (int off = 8; off >= 1; off >>= 1) {
#pragma unroll
            for (int j = 0; j < 8; j++) {
                if (j < off) sq[j] = __fadd_rn(sq[j], sq[j + off]);
            }
        }
        zh2 += __shfl_xor_sync(0xffffffff, zh2, 1);
        zl2 += __shfl_xor_sync(0xffffffff, zl2, 1);
        if (half == 0) {
            reinterpret_cast<float*>(smp + SM_ZN)[row] = sq[0];
            // B = Wmax*(2^-9*||zh|| + ||zl||), Wmax = 8/1024; D = 4B + slack + tie margin
            float nzh = __fsqrt_rn(zh2) * 1.0002f;
            float nzl = __fsqrt_rn(zl2) * 1.0002f + 1e-12f;
            float Bb = 7.9e-3f * (0.00196f * nzh + nzl);
            reinterpret_cast<float*>(smp + SM_E)[row] = 4.0f * Bb + 1.6e-4f;
        }
        if (tid < MROWS) cnts[tid] = 0;
    }
    __syncthreads();

    // ---- register-resident A fragments (zh only) ----
    uint32_t ah[4][4];
    {
        const float* r0 = reinterpret_cast<const float*>(smp) + (w * 16 + g) * Z_STRIDE;
        const float* r1 = r0 + 8 * Z_STRIDE;
#pragma unroll
        for (int kt = 0; kt < 4; kt++) {
            const int c0 = kt * 16 + 2 * t;
            ah[kt][0] = hi2(r0[c0],     r0[c0 + 1]);
            ah[kt][1] = hi2(r1[c0],     r1[c0 + 1]);
            ah[kt][2] = hi2(r0[c0 + 8], r0[c0 + 9]);
            ah[kt][3] = hi2(r1[c0 + 8], r1[c0 + 9]);
        }
    }
    const int rA = w * 16 + g;
    const float znA = reinterpret_cast<const float*>(smp + SM_ZN)[rA];
    const float znB = reinterpret_cast<const float*>(smp + SM_ZN)[rA + 8];
    const float DA = reinterpret_cast<const float*>(smp + SM_E)[rA];
    const float DB = reinterpret_cast<const float*>(smp + SM_E)[rA + 8];
    const unsigned long long zpkA = pk2(znA, znA);
    const unsigned long long zpkB = pk2(znB, znB);
    const unsigned long long NEG2 = pk2(-2.0f, -2.0f);

    // ---- prefetch chunk 0; load wnorm table ----
    issue_chunk(sb, 0, 0, tid); CP_COMMIT();
    {
        float* sWNl = reinterpret_cast<float*>(smp + SM_WN);
#pragma unroll
        for (int i = 0; i < KK / THREADS; i++)
            sWNl[tid + i * THREADS] = g_wnorm[tid + i * THREADS];
    }

    // ================= SWEEP 1: branchless min tracking only =================
    float rmA = 3.4e38f, rmB = 3.4e38f;
    for (int c = 0; c < NCHUNKS; c++) {
        CP_WAIT(0);
        __syncthreads();
        if (c + 1 < NCHUNKS) { issue_chunk(sb, c + 1, (c + 1) & 1, tid); CP_COMMIT(); }
        const char* bbase = smp + SM_B + (c & 1) * B_BUF;
#pragma unroll
        for (int nt = 0; nt < 4; nt++) {
            float d0, d1, d2, d3;
            nt_dists(smp, bbase, c, nt, g, t, ah, zpkA, zpkB, NEG2, d0, d1, d2, d3);
            rmA = fminf(rmA, fminf(d0, d1));
            rmB = fminf(rmB, fminf(d2, d3));
        }
    }
    // final row mins + tight thresholds
#pragma unroll
    for (int o = 1; o < 4; o <<= 1) {
        rmA = fminf(rmA, __shfl_xor_sync(0xffffffff, rmA, o));
        rmB = fminf(rmB, __shfl_xor_sync(0xffffffff, rmB, o));
    }
    const float thrA = rmA + DA;
    const float thrB = rmB + DB;

    // ================= SWEEP 2: recompute (bitwise identical), rare pushes ==
    // buf0 safe to overwrite: every thread passed sweep-1 c=31's barrier,
    // which orders all reads of buf0 (last read at c=30) before this point.
    issue_chunk(sb, 0, 0, tid); CP_COMMIT();
    for (int c = 0; c < NCHUNKS; c++) {
        CP_WAIT(0);
        __syncthreads();
        if (c + 1 < NCHUNKS) { issue_chunk(sb, c + 1, (c + 1) & 1, tid); CP_COMMIT(); }
        const char* bbase = smp + SM_B + (c & 1) * B_BUF;
#pragma unroll
        for (int nt = 0; nt < 4; nt++) {
            float d0, d1, d2, d3;
            nt_dists(smp, bbase, c, nt, g, t, ah, zpkA, zpkB, NEG2, d0, d1, d2, d3);
            const int cb = c * NC + nt * 8 + 2 * t;
            if (d0 <= thrA) { int p = atomicAdd(&cnts[rA], 1);     if (p < CAND_CAP) clist[rA * CAND_CAP + p] = (unsigned short)cb; }
            if (d1 <= thrA) { int p = atomicAdd(&cnts[rA], 1);     if (p < CAND_CAP) clist[rA * CAND_CAP + p] = (unsigned short)(cb + 1); }
            if (d2 <= thrB) { int p = atomicAdd(&cnts[rA + 8], 1); if (p < CAND_CAP) clist[(rA + 8) * CAND_CAP + p] = (unsigned short)cb; }
            if (d3 <= thrB) { int p = atomicAdd(&cnts[rA + 8], 1); if (p < CAND_CAP) clist[(rA + 8) * CAND_CAP + p] = (unsigned short)(cb + 1); }
        }
    }
    __syncthreads();   // all pushes visible

    // ---- refinement: exact dists over candidates (quad-parallel, lowest-idx ties) ----
    const float* zr0 = reinterpret_cast<const float*>(smp) + rA * Z_STRIDE;
    const float* zr1 = zr0 + 8 * Z_STRIDE;
    const float* sWN = reinterpret_cast<const float*>(smp + SM_WN);
    float bd0 = 3.4e38f, bd1 = 3.4e38f;
    int bi0 = KK, bi1 = KK;
    {
        int ctA = cnts[rA];
        if (ctA <= CAND_CAP) {
            for (int j = t; j < ctA; j += 4) {
                int idx = clist[rA * CAND_CAP + j];
                float de = exact_dist(zr0, idx, znA, sWN, W);
                if (de < bd0 || (de == bd0 && idx < bi0)) { bd0 = de; bi0 = idx; }
            }
        } else {   // overflow: exact full scan (correctness insurance, ~never)
            for (int idx = t; idx < KK; idx += 4) {
                float de = exact_dist(zr0, idx, znA, sWN, W);
                if (de < bd0 || (de == bd0 && idx < bi0)) { bd0 = de; bi0 = idx; }
            }
        }
        int ctB = cnts[rA + 8];
        if (ctB <= CAND_CAP) {
            for (int j = t; j < ctB; j += 4) {
                int idx = clist[(rA + 8) * CAND_CAP + j];
                float de = exact_dist(zr1, idx, znB, sWN, W);
                if (de < bd1 || (de == bd1 && idx < bi1)) { bd1 = de; bi1 = idx; }
            }
        } else {
            for (int idx = t; idx < KK; idx += 4) {
                float de = exact_dist(zr1, idx, znB, sWN, W);
                if (de < bd1 || (de == bd1 && idx < bi1)) { bd1 = de; bi1 = idx; }
            }
        }
    }

    // ---- quad reduce refined (smaller index wins ties) ----
#pragma unroll
    for (int o = 1; o < 4; o <<= 1) {
        float od = __shfl_xor_sync(0xffffffff, bd0, o);
        int   oi = __shfl_xor_sync(0xffffffff, bi0, o);
        if (od < bd0 || (od == bd0 && oi < bi0)) { bd0 = od; bi0 = oi; }
        od = __shfl_xor_sync(0xffffffff, bd1, o);
        oi = __shfl_xor_sync(0xffffffff, bi1, o);
        if (od < bd1 || (od == bd1 && oi < bi1)) { bd1 = od; bi1 = oi; }
    }
    const int h = t & 1;
    const int my = h ? bi1 : bi0;

    // ---- outputs: codes, z_q_st = z + (w - z), loss partial ----
    const int rown = rA + 8 * h;
    const int grow = blockIdx.x * MROWS + rown;
    if (t < 2) out_codes[grow] = (float)my;

    const int b = grow >> 13;
    const int tp = grow & (TT - 1);
    const int cbase = (t >> 1) * 32;             // this thread covers 32 dims
    const float* zrow = reinterpret_cast<const float*>(smp) + rown * Z_STRIDE;
    float* oz = out_zq + (size_t)b * DD * TT + tp;
    const float4* wrow = reinterpret_cast<const float4*>(W + (size_t)my * DD + cbase);
    float lsum = 0.0f;
#pragma unroll
    for (int j = 0; j < 8; j++) {
        float4 wv = wrow[j];
        float wa[4] = {wv.x, wv.y, wv.z, wv.w};
#pragma unroll
        for (int q = 0; q < 4; q++) {
            const int d = cbase + 4 * j + q;
            float zv = zrow[d];
            float e = __fsub_rn(wa[q], zv);
            oz[(size_t)d * TT] = __fadd_rn(zv, e);   // straight-through estimator
            lsum = __fadd_rn(lsum, __fmul_rn(e, e));
        }
    }

    float* sRed = reinterpret_cast<float*>(smp + SM_RED);
    sRed[tid] = lsum;
    __syncthreads();
#pragma unroll
    for (int s = THREADS / 2; s > 0; s >>= 1) {
        if (tid < s) sRed[tid] += sRed[tid + s];
        __syncthreads();
    }

    // ---- fused finalize: last block reduces all 1024 partials (deterministic order) ----
    __shared__ unsigned int sIsLast;
    if (tid == 0) {
        g_partial[blockIdx.x] = sRed[0];
        __threadfence();
        unsigned int tk = atomicAdd(&g_ticket, 1u);
        sIsLast = (tk == NBLOCKS - 1) ? 1u : 0u;
    }
    __syncthreads();
    if (sIsLast) {
        float v = 0.0f;
#pragma unroll
        for (int i = 0; i < NBLOCKS / THREADS; i++)
            v = __fadd_rn(v, g_partial[tid + i * THREADS]);
        sRed[tid] = v;
        __syncthreads();
#pragma unroll
        for (int s = THREADS / 2; s > 0; s >>= 1) {
            if (tid < s) sRed[tid] += sRed[tid + s];
            __syncthreads();
        }
        if (tid == 0) {
            out_loss[0] = 1.25f * (sRed[0] / (float)NZ);
            g_ticket = 0;    // reset for next graph replay
        }
    }
}

extern "C" void kernel_launch(void* const* d_in, const int* in_sizes, int n_in,
                              void* d_out, int out_size) {
    const float* z = (const float*)d_in[0];      // [8, 64, 8192]
    const float* W = (const float*)d_in[1];      // [1024, 64]
    float* out = (float*)d_out;
    float* out_zq    = out;
    float* out_loss  = out + NZ;
    float* out_codes = out + NZ + 1;

    vq_prep_kernel<<<32, 32>>>(W);
    vq_main_kernel<<<NBLOCKS, THREADS>>>(z, W, out_zq, out_codes, out_loss);
}